// round 3
// baseline (speedup 1.0000x reference)
#include <cuda_runtime.h>

#define LAMBDA_COORD 5.0f
#define LAMBDA_NO_OBJ 0.5f

#define NTHREADS 256
#define NBLOCKS  592   // 148 SMs * 4 CTAs = 1024 thr/SM; ~2.16 float4-iters/thread

__device__ float        g_sum  = 0.0f;
__device__ unsigned int g_done = 0;

__device__ __forceinline__ float warp_reduce(float v) {
    #pragma unroll
    for (int off = 16; off > 0; off >>= 1)
        v += __shfl_xor_sync(0xFFFFFFFFu, v, off);
    return v;
}

__global__ void __launch_bounds__(NTHREADS)
yolo_loss_kernel(
    const float*  __restrict__ main_boxes,   // [M,4]
    const float4* __restrict__ pred_boxes,   // [P]
    const float*  __restrict__ conf,         // [P]
    const float4* __restrict__ gmp,          // [NP4]
    const float4* __restrict__ gpp,          // [NP4]
    const int*    __restrict__ matched_main, // [P]
    const float*  __restrict__ matched_iou,  // [P]
    float* __restrict__ out,
    int P, int NP4)
{
    const int tid    = blockIdx.x * NTHREADS + threadIdx.x;
    const int stride = gridDim.x * NTHREADS;

    float acc = 0.0f;

    // ---- box loss first (its loads start early, overlap with prob loop) ----
    for (int p = tid; p < P; p += stride) {
        int   mm = matched_main[p];
        float c  = conf[p];
        if (mm >= 0) {
            float4 pb = pred_boxes[p];
            const float* mbp = main_boxes + (size_t)mm * 4;
            float mx = mbp[0], my = mbp[1], mw = mbp[2], mh = mbp[3];

            float dx = mx - pb.x;
            float dy = my - pb.y;
            float xy = dx * dx + dy * dy;

            float sw = sqrtf(fmaxf(mw, 0.0f)) - sqrtf(fmaxf(pb.z, 0.0f));
            float sh = sqrtf(fmaxf(mh, 0.0f)) - sqrtf(fmaxf(pb.w, 0.0f));
            float wh = sw * sw + sh * sh;

            float di = matched_iou[p] - c;
            acc += LAMBDA_COORD * (xy + wh) + di * di;
        } else {
            acc += LAMBDA_NO_OBJ * c * c;
        }
    }

    // ---- prob loss: 2x unrolled, 4 independent LDG.128 batched up front ----
    int i = tid;
    for (; i + stride < NP4; i += 2 * stride) {
        float4 a0 = gmp[i];
        float4 b0 = gpp[i];
        float4 a1 = gmp[i + stride];
        float4 b1 = gpp[i + stride];

        float d0 = a0.x - b0.x, d1 = a0.y - b0.y, d2 = a0.z - b0.z, d3 = a0.w - b0.w;
        acc = fmaf(d0, d0, acc); acc = fmaf(d1, d1, acc);
        acc = fmaf(d2, d2, acc); acc = fmaf(d3, d3, acc);

        float e0 = a1.x - b1.x, e1 = a1.y - b1.y, e2 = a1.z - b1.z, e3 = a1.w - b1.w;
        acc = fmaf(e0, e0, acc); acc = fmaf(e1, e1, acc);
        acc = fmaf(e2, e2, acc); acc = fmaf(e3, e3, acc);
    }
    for (; i < NP4; i += stride) {
        float4 a = gmp[i];
        float4 b = gpp[i];
        float d0 = a.x - b.x, d1 = a.y - b.y, d2 = a.z - b.z, d3 = a.w - b.w;
        acc = fmaf(d0, d0, acc); acc = fmaf(d1, d1, acc);
        acc = fmaf(d2, d2, acc); acc = fmaf(d3, d3, acc);
    }

    // ---- block reduction ----
    __shared__ float warp_sums[NTHREADS >> 5];
    __shared__ bool  is_last;
    float wsum = warp_reduce(acc);
    int lane = threadIdx.x & 31;
    int wid  = threadIdx.x >> 5;
    if (lane == 0) warp_sums[wid] = wsum;
    __syncthreads();

    if (wid == 0) {
        float v = (lane < (NTHREADS >> 5)) ? warp_sums[lane] : 0.0f;
        v = warp_reduce(v);
        if (lane == 0) {
            // overlapped accumulation into a single scalar; ordered before the
            // done-count by a fence so the last block sees all contributions.
            atomicAdd(&g_sum, v);
            __threadfence();
            unsigned int prev = atomicAdd(&g_done, 1u);
            is_last = (prev == (unsigned int)(gridDim.x - 1));
        }
    }
    __syncthreads();

    if (is_last && threadIdx.x == 0) {
        // coherent read via atomic (bypasses any stale L1 line)
        float total = atomicAdd(&g_sum, 0.0f);
        out[0] = total;
        // reset for the next graph replay
        g_sum  = 0.0f;
        g_done = 0;
        __threadfence();
    }
}

extern "C" void kernel_launch(void* const* d_in, const int* in_sizes, int n_in,
                              void* d_out, int out_size) {
    const float*  main_boxes   = (const float*) d_in[0];
    const float4* pred_boxes   = (const float4*)d_in[1];
    const float*  conf         = (const float*) d_in[2];
    const float4* gmp          = (const float4*)d_in[3];
    const float4* gpp          = (const float4*)d_in[4];
    const int*    matched_main = (const int*)   d_in[5];
    const float*  matched_iou  = (const float*) d_in[6];
    float* out = (float*)d_out;

    int P   = in_sizes[2];      // 32768
    int NP4 = in_sizes[3] / 4;  // 327680

    yolo_loss_kernel<<<NBLOCKS, NTHREADS>>>(
        main_boxes, pred_boxes, conf, gmp, gpp, matched_main, matched_iou,
        out, P, NP4);
}

// round 4
// speedup vs baseline: 1.0934x; 1.0934x over previous
#include <cuda_runtime.h>

#define LAMBDA_COORD 5.0f
#define LAMBDA_NO_OBJ 0.5f

#define NTHREADS 256
#define NBLOCKS  296   // empirical best (R1); 75,776 threads

__global__ void zero_out_kernel(float* out) {
    out[0] = 0.0f;
}

__device__ __forceinline__ float warp_reduce(float v) {
    #pragma unroll
    for (int off = 16; off > 0; off >>= 1)
        v += __shfl_xor_sync(0xFFFFFFFFu, v, off);
    return v;
}

__global__ void __launch_bounds__(NTHREADS)
yolo_loss_kernel(
    const float*  __restrict__ main_boxes,   // [M,4]
    const float4* __restrict__ pred_boxes,   // [P]
    const float*  __restrict__ conf,         // [P]
    const float4* __restrict__ gmp,          // [NP4]
    const float4* __restrict__ gpp,          // [NP4]
    const int*    __restrict__ matched_main, // [P]
    const float*  __restrict__ matched_iou,  // [P]
    float* __restrict__ out,
    int P, int NP4)
{
    const int tid    = blockIdx.x * NTHREADS + threadIdx.x;
    const int stride = NBLOCKS * NTHREADS;   // compile-time constant stride

    float acc = 0.0f;

    // ---- prob loss: 4-deep front-batched loads -> ~1 DRAM latency round ----
    int i = tid;
    for (; i + 3 * stride < NP4; i += 4 * stride) {
        // issue all 8 independent LDG.128 before any compute
        float4 a0 = gmp[i];
        float4 a1 = gmp[i + stride];
        float4 a2 = gmp[i + 2 * stride];
        float4 a3 = gmp[i + 3 * stride];
        float4 b0 = gpp[i];
        float4 b1 = gpp[i + stride];
        float4 b2 = gpp[i + 2 * stride];
        float4 b3 = gpp[i + 3 * stride];

        float d;
        d = a0.x - b0.x; acc = fmaf(d, d, acc);
        d = a0.y - b0.y; acc = fmaf(d, d, acc);
        d = a0.z - b0.z; acc = fmaf(d, d, acc);
        d = a0.w - b0.w; acc = fmaf(d, d, acc);
        d = a1.x - b1.x; acc = fmaf(d, d, acc);
        d = a1.y - b1.y; acc = fmaf(d, d, acc);
        d = a1.z - b1.z; acc = fmaf(d, d, acc);
        d = a1.w - b1.w; acc = fmaf(d, d, acc);
        d = a2.x - b2.x; acc = fmaf(d, d, acc);
        d = a2.y - b2.y; acc = fmaf(d, d, acc);
        d = a2.z - b2.z; acc = fmaf(d, d, acc);
        d = a2.w - b2.w; acc = fmaf(d, d, acc);
        d = a3.x - b3.x; acc = fmaf(d, d, acc);
        d = a3.y - b3.y; acc = fmaf(d, d, acc);
        d = a3.z - b3.z; acc = fmaf(d, d, acc);
        d = a3.w - b3.w; acc = fmaf(d, d, acc);
    }
    for (; i < NP4; i += stride) {
        float4 a = gmp[i];
        float4 b = gpp[i];
        float d;
        d = a.x - b.x; acc = fmaf(d, d, acc);
        d = a.y - b.y; acc = fmaf(d, d, acc);
        d = a.z - b.z; acc = fmaf(d, d, acc);
        d = a.w - b.w; acc = fmaf(d, d, acc);
    }

    // ---- box loss: <1 iter per thread at this grid ----
    for (int p = tid; p < P; p += stride) {
        int   mm = matched_main[p];
        float c  = conf[p];
        if (mm >= 0) {
            float4 pb = pred_boxes[p];
            const float* mbp = main_boxes + (size_t)mm * 4;
            float mx = mbp[0], my = mbp[1], mw = mbp[2], mh = mbp[3];

            float dx = mx - pb.x;
            float dy = my - pb.y;
            float xy = dx * dx + dy * dy;

            float sw = sqrtf(fmaxf(mw, 0.0f)) - sqrtf(fmaxf(pb.z, 0.0f));
            float sh = sqrtf(fmaxf(mh, 0.0f)) - sqrtf(fmaxf(pb.w, 0.0f));
            float wh = sw * sw + sh * sh;

            float di = matched_iou[p] - c;
            acc += LAMBDA_COORD * (xy + wh) + di * di;
        } else {
            acc += LAMBDA_NO_OBJ * c * c;
        }
    }

    // ---- block reduction + direct atomic into out (overlapped across blocks) ----
    __shared__ float warp_sums[NTHREADS >> 5];
    float wsum = warp_reduce(acc);
    int lane = threadIdx.x & 31;
    int wid  = threadIdx.x >> 5;
    if (lane == 0) warp_sums[wid] = wsum;
    __syncthreads();

    if (wid == 0) {
        float v = (lane < (NTHREADS >> 5)) ? warp_sums[lane] : 0.0f;
        v = warp_reduce(v);
        if (lane == 0) atomicAdd(out, v);
    }
}

extern "C" void kernel_launch(void* const* d_in, const int* in_sizes, int n_in,
                              void* d_out, int out_size) {
    const float*  main_boxes   = (const float*) d_in[0];
    const float4* pred_boxes   = (const float4*)d_in[1];
    const float*  conf         = (const float*) d_in[2];
    const float4* gmp          = (const float4*)d_in[3];
    const float4* gpp          = (const float4*)d_in[4];
    const int*    matched_main = (const int*)   d_in[5];
    const float*  matched_iou  = (const float*) d_in[6];
    float* out = (float*)d_out;

    int P   = in_sizes[2];      // 32768
    int NP4 = in_sizes[3] / 4;  // 327680

    zero_out_kernel<<<1, 1>>>(out);
    yolo_loss_kernel<<<NBLOCKS, NTHREADS>>>(
        main_boxes, pred_boxes, conf, gmp, gpp, matched_main, matched_iou,
        out, P, NP4);
}